// round 13
// baseline (speedup 1.0000x reference)
#include <cuda_runtime.h>

// Segment-sum over sorted ray_indices + gather back.
// Output: d_out[0 .. n_rays*8)                    = per-ray sums
//         d_out[n_rays*8 .. n_rays*8+n_samples*8) = per-sample gathered sums
//
// Sorted indices => each ray is a contiguous pack.
//   1) boundary_kernel: streaming pass over idx -> pack offsets (static
//      __device__ scratch, no alloc).
//   2) fused raysum+scatter: one warp per ray. Software-pipelined 2-deep
//      load loop (double-buffered -> up to 4 LDG.128 in flight/warp),
//      parity-preserving butterfly, per-ray sum write + broadcast scatter.

#define MAX_RAYS_PAD (1 << 20)
__device__ int g_off[MAX_RAYS_PAD + 1];

// ---------------- boundary kernel ----------------
#define BBLOCK 256
#define BRUN 16
#define B_SAMPLES (BBLOCK * BRUN)

__global__ void __launch_bounds__(BBLOCK)
boundary_kernel(const int* __restrict__ idx,
                int n_samples, int n_rays) {
    const int lane = threadIdx.x & 31;
    int base = (blockIdx.x * BBLOCK + threadIdx.x) * BRUN;
    const bool active = base < n_samples;
    int cnt = 0;

    int r[BRUN];
    if (active) {
        cnt = (base + BRUN <= n_samples) ? BRUN : (n_samples - base);
        if (cnt == BRUN) {
            const int4* p = reinterpret_cast<const int4*>(idx + base);
            #pragma unroll
            for (int q = 0; q < BRUN / 4; q++) {
                int4 v = p[q];
                r[q * 4 + 0] = v.x; r[q * 4 + 1] = v.y;
                r[q * 4 + 2] = v.z; r[q * 4 + 3] = v.w;
            }
        } else {
            for (int s = 0; s < BRUN; s++) r[s] = (s < cnt) ? idx[base + s] : 0;
        }
    } else {
        #pragma unroll
        for (int s = 0; s < BRUN; s++) r[s] = 0;
    }

    // prev = preceding thread's last element via shuffle; only lane 0 does a
    // scalar global load.
    int prev = __shfl_up_sync(0xFFFFFFFFu, r[BRUN - 1], 1);
    if (lane == 0) prev = (base == 0) ? -1 : (active ? idx[base - 1] : 0);
    if (!active) return;

    #pragma unroll
    for (int s = 0; s < BRUN; s++) {
        if (s >= cnt) break;
        if (r[s] != prev) {
            for (int q = prev + 1; q <= r[s]; q++) g_off[q] = base + s;
        }
        prev = r[s];
    }
    if (base + cnt == n_samples) {
        for (int q = prev + 1; q <= n_rays; q++) g_off[q] = n_samples;
    }
}

// ------- fused ray-sum + scatter kernel: one warp per ray -------
#define RSBLOCK 256
#define RAYS_PER_BLOCK (RSBLOCK / 32)

__global__ void __launch_bounds__(RSBLOCK, 7)
raysum_scatter_kernel(const float4* __restrict__ vals,  // 2 float4 per sample
                      float4* __restrict__ sums,        // 2 float4 per ray
                      float4* __restrict__ out,         // 2 float4 per sample
                      int n_rays) {
    int warp = threadIdx.x >> 5;
    int lane = threadIdx.x & 31;
    int ray = blockIdx.x * RAYS_PER_BLOCK + warp;
    if (ray >= n_rays) return;

    // 32-bit indices: n_samples*2 = 8.4M fits comfortably.
    int a2 = g_off[ray] * 2;          // even -> lane parity == f4 parity
    int b2 = g_off[ray + 1] * 2;

    float4 acc = make_float4(0.f, 0.f, 0.f, 0.f);

    // Software-pipelined 2-wide load loop: iteration i+1's loads issue
    // before iteration i's values are consumed -> up to 4 LDG in flight.
    int j = a2 + lane;
    float4 v0, v1;
    bool has = (j + 32 < b2);
    if (has) {
        v0 = __ldcs(vals + j);
        v1 = __ldcs(vals + j + 32);
    }
    while (has) {
        int jn = j + 64;
        bool hasn = (jn + 32 < b2);
        float4 w0, w1;
        if (hasn) {
            w0 = __ldcs(vals + jn);
            w1 = __ldcs(vals + jn + 32);
        }
        acc.x += v0.x; acc.y += v0.y; acc.z += v0.z; acc.w += v0.w;
        acc.x += v1.x; acc.y += v1.y; acc.z += v1.z; acc.w += v1.w;
        v0 = w0; v1 = w1;
        j = jn; has = hasn;
    }
    // Tail: after the loop, j+32 >= b2, so at most one element remains.
    if (j < b2) {
        float4 v = __ldcs(vals + j);
        acc.x += v.x; acc.y += v.y; acc.z += v.z; acc.w += v.w;
    }

    // Butterfly over even strides: every lane ends with the total for its
    // own parity (lane parity == float4-half parity).
    #pragma unroll
    for (int d = 2; d < 32; d <<= 1) {
        acc.x += __shfl_xor_sync(0xFFFFFFFFu, acc.x, d);
        acc.y += __shfl_xor_sync(0xFFFFFFFFu, acc.y, d);
        acc.z += __shfl_xor_sync(0xFFFFFFFFu, acc.z, d);
        acc.w += __shfl_xor_sync(0xFFFFFFFFu, acc.w, d);
    }

    // Per-ray sum: lane 0 holds half-0, lane 1 holds half-1.
    if (lane < 2) sums[ray * 2 + lane] = acc;

    // Scatter the broadcast sum over the ray's contiguous output region.
    // out[j] parity == lane parity, so each lane stores its own acc.
    j = a2 + lane;
    for (; j + 32 < b2; j += 64) {
        __stcs(out + j, acc);
        __stcs(out + j + 32, acc);
    }
    if (j < b2) __stcs(out + j, acc);
}

extern "C" void kernel_launch(void* const* d_in, const int* in_sizes, int n_in,
                              void* d_out, int out_size) {
    const float4* vals = (const float4*)d_in[0];
    const int* idx = (const int*)d_in[1];

    int n_samples = in_sizes[1];                 // 4194304
    int n_rays = out_size / 8 - n_samples;       // 65536

    float4* sums = (float4*)d_out;                                    // [n_rays*2] float4
    float4* out_ps = (float4*)((float*)d_out + (size_t)n_rays * 8);   // [n_samples*2] float4

    // 1) ray pack offsets (one streaming pass over idx)
    {
        long long blocks = ((long long)n_samples + B_SAMPLES - 1) / B_SAMPLES;
        boundary_kernel<<<(unsigned)blocks, BBLOCK>>>(idx, n_samples, n_rays);
    }

    // 2) fused: one warp per ray -> sum + per-ray write + scatter write
    {
        long long blocks = ((long long)n_rays + RAYS_PER_BLOCK - 1) / RAYS_PER_BLOCK;
        raysum_scatter_kernel<<<(unsigned)blocks, RSBLOCK>>>(vals, sums, out_ps,
                                                             n_rays);
    }
}